// round 12
// baseline (speedup 1.0000x reference)
#include <cuda_runtime.h>
#include <math.h>

// ---------------------------------------------------------------------------
// YOLOv3 loss, B=32. Layers: 13x13 / 26x26 / 52x52, 3 anchors, 80 classes.
// y_true: (32, 3549, 3, 85) fp32 ; preds: (32,H,W,255) fp32 ; out: (32,) fp32
//
//  k_mask <<<672,256>>> : per (b,layer,chunk-of-512): obj bitmask via ballot.
//                         Block 0 zeroes out.
//  k_main <<<1440,256>>>: blocks [0,96)     -> positive xy/wh/cls loss
//                         blocks [96,1440)  -> conf-BCE + IoU-ignore,
//                         1 anchor/thread, hoisted loads, box list rebuilt per
//                         block from the mask (prefix scan).
// Scattered bulk loads use PLAIN global loads (not __ldg/.nc): testing the
// hypothesis that the nc/texture path fetches full 128B lines per miss
// (observed ~128 B DRAM per 20 B window) while the normal LDG path fetches
// 32 B sectors -> ~2.8x DRAM-byte reduction on the dominant streams.
// ---------------------------------------------------------------------------

#define NB    32
#define NBL   96
#define PMAX  128
#define FULLM 0xffffffffu

__device__ unsigned g_mask[NBL * 256];   // word w of segment bl = anchors [32w,32w+32)

__constant__ float c_anc[9][2] = {
    {116.f, 90.f}, {156.f, 198.f}, {373.f, 326.f},
    { 30.f, 61.f}, { 62.f,  45.f}, { 59.f, 119.f},
    { 10.f, 13.f}, { 16.f,  30.f}, { 33.f,  23.f}};

__device__ __forceinline__ float sigf(float x) {
    return __fdividef(1.f, 1.f + __expf(-x));
}
// bce_logits(t, x) for x in (0,1): max(x,0)=x, |x|=x
__device__ __forceinline__ float bce01(float t, float x) {
    return x - x * t + __logf(1.f + __expf(-x));
}

// ============================ k_mask =========================================
// r in [0,21) -> (layer, chunk of 512)
__device__ __forceinline__ void rmap21(int r, int& layer, int& chunk) {
    if (r == 0)      { layer = 0; chunk = 0; }
    else if (r < 5)  { layer = 1; chunk = r - 1; }
    else             { layer = 2; chunk = r - 5; }
}

__global__ __launch_bounds__(256)
void k_mask(const float* __restrict__ yt, float* __restrict__ out) {
    int blk = blockIdx.x;
    if (blk == 0 && threadIdx.x < NB) out[threadIdx.x] = 0.f;

    int b = blk / 21, r = blk - b * 21;
    int layer, chunk;
    rmap21(r, layer, chunk);
    int seglen  = (layer == 0) ? 507 : (layer == 1) ? 2028 : 8112;
    int celloff = (layer == 0) ? 0   : (layer == 1) ? 169  : 845;
    int bl = b * 3 + layer;
    const float* __restrict__ segbase = yt + ((size_t)b * 3549 + celloff) * 255;

    int lane = threadIdx.x & 31;
    int loc0 = chunk * 512 + threadIdx.x;
    int loc1 = loc0 + 256;
    bool p0 = (loc0 < seglen) && (segbase[(size_t)loc0 * 85] > 0.5f);
    bool p1 = (loc1 < seglen) && (segbase[(size_t)loc1 * 85] > 0.5f);
    unsigned m0 = __ballot_sync(FULLM, p0);
    unsigned m1 = __ballot_sync(FULLM, p1);
    if (lane == 0) {
        g_mask[bl * 256 + (loc0 >> 5)] = m0;
        g_mask[bl * 256 + (loc1 >> 5)] = m1;
    }
}

// ============================ box-list rebuild ===============================
// Ordered compaction of set mask bits (ascending anchor index == exact stable
// top-k membership). Returns total positives.
__device__ int build_list(int bl, int nword, const float* __restrict__ segbase,
                          float4* sA, float* sArea, int* s_loc, int* s_wtot) {
    int tid = threadIdx.x, wid = tid >> 5, lane = tid & 31;
    unsigned w = (tid < nword) ? g_mask[bl * 256 + tid] : 0u;
    int c = __popc(w);

    // inclusive warp scan of c
    int sc = c;
    #pragma unroll
    for (int o = 1; o < 32; o <<= 1) {
        int v = __shfl_up_sync(FULLM, sc, o);
        if (lane >= o) sc += v;
    }
    if (lane == 31) s_wtot[wid] = sc;
    __syncthreads();
    int wbase = 0, total = 0;
    #pragma unroll
    for (int i = 0; i < 8; i++) {
        int t = s_wtot[i];
        wbase += (i < wid) ? t : 0;
        total += t;
    }
    int slot = wbase + sc - c;     // exclusive prefix for this thread's word

    unsigned ww = w;
    while (ww) {
        int bit = __ffs(ww) - 1;
        ww &= ww - 1;
        int loc = tid * 32 + bit;
        if (s_loc && slot < PMAX) s_loc[slot] = loc;
        if (slot < 64) {
            const float* tb = segbase + (size_t)loc * 85;
            float t1 = tb[1], t2 = tb[2], t3 = tb[3], t4 = tb[4];
            sA[slot] = make_float4(t1 - 0.5f * t3, t2 - 0.5f * t4,
                                   t1 + 0.5f * t3, t2 + 0.5f * t4);
            sArea[slot] = t3 * t4;
        }
        slot++;
    }
    __syncthreads();
    return total;
}

// ============================ conf path ======================================
template<int W, int LAYER, int CELLOFF, int NWORD>
__device__ float conf_work(int b, int bl, int chunk,
                           const float* __restrict__ yt,
                           const float* __restrict__ pred,
                           float4* sA, float* sArea, int* s_wtot) {
    constexpr int SEGLEN = W * W * 3;
    constexpr float invW = 1.f / (float)W;
    const float* __restrict__ segbase = yt + ((size_t)b * 3549 + CELLOFF) * 255;

    // ---- hoisted loads (issued before the barrier-laden scan)
    int loc = chunk * 256 + threadIdx.x;
    bool valid = (loc < SEGLEN);
    int locc = valid ? loc : 0;
    const float* __restrict__ pb =
        pred + (size_t)b * (W * W * 255) + (size_t)locc * 85;
    float q0 = pb[0];
    float q1 = pb[1], q2 = pb[2];
    float q3 = pb[3], q4 = pb[4];
    unsigned mw = g_mask[bl * 256 + (locc >> 5)];
    bool objb = (mw >> (locc & 31)) & 1u;

    int total = build_list(bl, NWORD, segbase, sA, sArea, nullptr, s_wtot);
    int cnt = min(total, 64);

    // ---- geometry + conf bce
    int cell = locc / 3, a = locc - cell * 3;
    int hh = cell / W, ww = cell - hh * W;
    float aw = c_anc[3 * LAYER + a][0];
    float ah = c_anc[3 * LAYER + a][1];
    float bx = (sigf(q1) + (float)ww) * invW;
    float by = (sigf(q2) + (float)hh) * invW;
    float bw = __expf(q3) * (aw * invW);
    float bh = __expf(q4) * (ah * invW);
    float hx = 0.5f * bw, hy = 0.5f * bh;
    float pminx = bx - hx, pmaxx = bx + hx;
    float pminy = by - hy, pmaxy = by + hy;
    float pa = bw * bh;
    float cb = bce01(objb ? 1.f : 0.f, sigf(q0));

    bool hit = false;
    for (int k = 0; k < cnt; k++) {
        float4 A = sA[k];
        float iw = fminf(pmaxx, A.z) - fmaxf(pminx, A.x);
        float ih = fminf(pmaxy, A.w) - fmaxf(pminy, A.y);
        float inter = fmaxf(iw, 0.f) * fmaxf(ih, 0.f);
        hit = hit || (3.f * inter >= pa + sArea[k]);   // iou >= 0.5
    }

    return valid ? cb * (objb ? 1.f : (hit ? 0.f : 1.f)) : 0.f;
}

// ============================ positive path ==================================
template<int W, int LAYER, int CELLOFF, int NWORD>
__device__ void pos_work(int b, int bl,
                         const float* __restrict__ yt,
                         const float* __restrict__ pred,
                         float* __restrict__ out,
                         float4* sA, float* sArea, int* s_loc, int* s_wtot,
                         float* s_red) {
    constexpr float fW = (float)W;
    constexpr float invW = 1.f / (float)W;
    const float* __restrict__ segbase = yt + ((size_t)b * 3549 + CELLOFF) * 255;
    int total = build_list(bl, NWORD, segbase, sA, sArea, s_loc, s_wtot);
    int pcnt = min(total, PMAX);
    if (pcnt == 0) return;

    const float* __restrict__ pbase = pred + (size_t)b * (W * W * 255);
    int wid = threadIdx.x >> 5, lane = threadIdx.x & 31;

    float acc = 0.f;
    for (int k = wid; k < pcnt; k += 8) {
        int loc = s_loc[k];
        int cell = loc / 3, a = loc - cell * 3;
        int hh = cell / W, ww = cell - hh * W;
        const float* tb = segbase + (size_t)loc * 85;
        const float* pb = pbase + (size_t)loc * 85;
        float aw = c_anc[3 * LAYER + a][0];
        float ah = c_anc[3 * LAYER + a][1];

        // group 0: channels 1..32
        float t0 = tb[lane + 1], q0 = pb[lane + 1];
        float tw = __shfl_sync(FULLM, t0, 2);    // yt ch3
        float th = __shfl_sync(FULLM, t0, 3);    // yt ch4
        float scale = 2.f - tw * th;
        float l = 0.f;
        if (lane == 0) {          // x
            float x = (sigf(q0) + (float)ww) * invW;
            float t = t0 * fW - (float)ww;
            l = scale * bce01(t, x);
        } else if (lane == 1) {   // y
            float x = (sigf(q0) + (float)hh) * invW;
            float t = t0 * fW - (float)hh;
            l = scale * bce01(t, x);
        } else if (lane == 2) {   // w
            float wp = __expf(q0) * aw * invW;
            float t = __logf(t0 * (416.f / aw));
            float d = t - wp;
            l = scale * 0.5f * d * d;
        } else if (lane == 3) {   // h
            float hp = __expf(q0) * ah * invW;
            float t = __logf(t0 * (416.f / ah));
            float d = t - hp;
            l = scale * 0.5f * d * d;
        } else {                  // cls channels 5..32
            l = bce01(t0, sigf(q0));
        }
        // group 1: channels 33..64 (cls)
        float t1 = tb[lane + 33], q1 = pb[lane + 33];
        l += bce01(t1, sigf(q1));
        // group 2: channels 65..84 (cls)
        if (lane < 20) {
            float t2 = tb[lane + 65], q2 = pb[lane + 65];
            l += bce01(t2, sigf(q2));
        }
        acc += l;
    }
    #pragma unroll
    for (int o = 16; o; o >>= 1) acc += __shfl_xor_sync(FULLM, acc, o);
    if (lane == 0) s_red[wid] = acc;
    __syncthreads();
    if (threadIdx.x == 0) {
        float v = 0.f;
        #pragma unroll
        for (int i = 0; i < 8; i++) v += s_red[i];
        if (v != 0.f) atomicAdd(out + b, v);
    }
}

// ============================ k_main =========================================
// conf r in [0,42): r<2 -> L0 chunk r ; r<10 -> L1 chunk r-2 ; else L2 chunk r-10
__global__ __launch_bounds__(256, 8)
void k_main(const float* __restrict__ yt,
            const float* __restrict__ p13,
            const float* __restrict__ p26,
            const float* __restrict__ p52,
            float* __restrict__ out) {
    __shared__ float4 sA[64];
    __shared__ float  sArea[64];
    __shared__ int    s_loc[PMAX];
    __shared__ int    s_wtot[8];
    __shared__ float  s_red[8];

    int blk = blockIdx.x;
    if (blk < NBL) {
        int b = blk / 3, layer = blk - b * 3;
        if (layer == 0)
            pos_work<13, 0, 0, 16>  (b, blk, yt, p13, out, sA, sArea, s_loc, s_wtot, s_red);
        else if (layer == 1)
            pos_work<26, 1, 169, 64>(b, blk, yt, p26, out, sA, sArea, s_loc, s_wtot, s_red);
        else
            pos_work<52, 2, 845, 254>(b, blk, yt, p52, out, sA, sArea, s_loc, s_wtot, s_red);
        return;
    }

    blk -= NBL;
    int b = blk / 42, r = blk - b * 42;
    int layer = (r < 2) ? 0 : (r < 10) ? 1 : 2;
    int chunk = (r < 2) ? r : (r < 10) ? r - 2 : r - 10;
    int bl = b * 3 + layer;

    float lsum;
    if (layer == 0)
        lsum = conf_work<13, 0, 0, 16>  (b, bl, chunk, yt, p13, sA, sArea, s_wtot);
    else if (layer == 1)
        lsum = conf_work<26, 1, 169, 64>(b, bl, chunk, yt, p26, sA, sArea, s_wtot);
    else
        lsum = conf_work<52, 2, 845, 254>(b, bl, chunk, yt, p52, sA, sArea, s_wtot);

    #pragma unroll
    for (int o = 16; o; o >>= 1) lsum += __shfl_xor_sync(FULLM, lsum, o);
    int wid = threadIdx.x >> 5, lane = threadIdx.x & 31;
    if (lane == 0) s_red[wid] = lsum;
    __syncthreads();
    if (threadIdx.x == 0) {
        float v = 0.f;
        #pragma unroll
        for (int i = 0; i < 8; i++) v += s_red[i];
        atomicAdd(out + b, v);
    }
}

// ---------------------------------------------------------------------------
extern "C" void kernel_launch(void* const* d_in, const int* in_sizes, int n_in,
                              void* d_out, int out_size) {
    const float* yt  = (const float*)d_in[0];
    const float* p13 = (const float*)d_in[1];
    const float* p26 = (const float*)d_in[2];
    const float* p52 = (const float*)d_in[3];
    float* out = (float*)d_out;

    k_mask<<<NB * 21, 256>>>(yt, out);
    k_main<<<NBL + NB * 42, 256>>>(yt, p13, p26, p52, out);
}

// round 13
// speedup vs baseline: 1.1345x; 1.1345x over previous
#include <cuda_runtime.h>
#include <math.h>

// ---------------------------------------------------------------------------
// YOLOv3 loss, B=32. Layers: 13x13 / 26x26 / 52x52, 3 anchors, 80 classes.
// y_true: (32, 3549, 3, 85) fp32 ; preds: (32,H,W,255) fp32 ; out: (32,) fp32
//
//  k_mask <<<672,256>>> : per (b,layer,chunk-of-512): obj bitmask via ballot.
//                         Block 0 zeroes out.
//  k_main <<<768,256>>> : blocks [0,96)   -> positive xy/wh/cls loss
//                         blocks [96,768) -> conf-BCE + IoU-ignore, 2 anch/thr.
//  k_main is launched with PROGRAMMATIC DEPENDENT LAUNCH: it starts while
//  k_mask still runs, issues its (k_mask-independent) pred loads, then
//  cudaGridDependencySynchronize() before reading g_mask. This removes the
//  launch gap + mask serialization that cost 0.5-2.6us across prior rounds.
// ---------------------------------------------------------------------------

#define NB    32
#define NBL   96
#define PMAX  128
#define FULLM 0xffffffffu

__device__ unsigned g_mask[NBL * 256];   // word w of segment bl = anchors [32w,32w+32)

__constant__ float c_anc[9][2] = {
    {116.f, 90.f}, {156.f, 198.f}, {373.f, 326.f},
    { 30.f, 61.f}, { 62.f,  45.f}, { 59.f, 119.f},
    { 10.f, 13.f}, { 16.f,  30.f}, { 33.f,  23.f}};

__device__ __forceinline__ float sigf(float x) {
    return __fdividef(1.f, 1.f + __expf(-x));
}
// bce_logits(t, x) for x in (0,1): max(x,0)=x, |x|=x
__device__ __forceinline__ float bce01(float t, float x) {
    return x - x * t + __logf(1.f + __expf(-x));
}

// r in [0,21) -> (layer, chunk of 512)
__device__ __forceinline__ void rmap21(int r, int& layer, int& chunk) {
    if (r == 0)      { layer = 0; chunk = 0; }
    else if (r < 5)  { layer = 1; chunk = r - 1; }
    else             { layer = 2; chunk = r - 5; }
}

// ============================ k_mask =========================================
__global__ __launch_bounds__(256)
void k_mask(const float* __restrict__ yt, float* __restrict__ out) {
    int blk = blockIdx.x;
    if (blk == 0 && threadIdx.x < NB) out[threadIdx.x] = 0.f;

    int b = blk / 21, r = blk - b * 21;
    int layer, chunk;
    rmap21(r, layer, chunk);
    int seglen  = (layer == 0) ? 507 : (layer == 1) ? 2028 : 8112;
    int celloff = (layer == 0) ? 0   : (layer == 1) ? 169  : 845;
    int bl = b * 3 + layer;
    const float* segbase = yt + ((size_t)b * 3549 + celloff) * 255;

    int lane = threadIdx.x & 31;
    int loc0 = chunk * 512 + threadIdx.x;
    int loc1 = loc0 + 256;
    bool p0 = (loc0 < seglen) && (__ldg(segbase + (size_t)loc0 * 85) > 0.5f);
    bool p1 = (loc1 < seglen) && (__ldg(segbase + (size_t)loc1 * 85) > 0.5f);
    unsigned m0 = __ballot_sync(FULLM, p0);
    unsigned m1 = __ballot_sync(FULLM, p1);
    if (lane == 0) {
        g_mask[bl * 256 + (loc0 >> 5)] = m0;
        g_mask[bl * 256 + (loc1 >> 5)] = m1;
    }
}

// ============================ box-list rebuild ===============================
// Ordered compaction of set mask bits (ascending anchor index == exact stable
// top-k membership). Returns total positives.
__device__ int build_list(int bl, int nword, const float* __restrict__ segbase,
                          float4* sA, float* sArea, int* s_loc, int* s_wtot) {
    int tid = threadIdx.x, wid = tid >> 5, lane = tid & 31;
    unsigned w = (tid < nword) ? g_mask[bl * 256 + tid] : 0u;
    int c = __popc(w);

    // inclusive warp scan of c
    int sc = c;
    #pragma unroll
    for (int o = 1; o < 32; o <<= 1) {
        int v = __shfl_up_sync(FULLM, sc, o);
        if (lane >= o) sc += v;
    }
    if (lane == 31) s_wtot[wid] = sc;
    __syncthreads();
    int wbase = 0, total = 0;
    #pragma unroll
    for (int i = 0; i < 8; i++) {
        int t = s_wtot[i];
        wbase += (i < wid) ? t : 0;
        total += t;
    }
    int slot = wbase + sc - c;     // exclusive prefix for this thread's word

    unsigned ww = w;
    while (ww) {
        int bit = __ffs(ww) - 1;
        ww &= ww - 1;
        int loc = tid * 32 + bit;
        if (s_loc && slot < PMAX) s_loc[slot] = loc;
        if (slot < 64) {
            const float* tb = segbase + (size_t)loc * 85;
            float t1 = __ldg(tb + 1), t2 = __ldg(tb + 2);
            float t3 = __ldg(tb + 3), t4 = __ldg(tb + 4);
            sA[slot] = make_float4(t1 - 0.5f * t3, t2 - 0.5f * t4,
                                   t1 + 0.5f * t3, t2 + 0.5f * t4);
            sArea[slot] = t3 * t4;
        }
        slot++;
    }
    __syncthreads();
    return total;
}

// ============================ conf path ======================================
template<int W, int LAYER, int CELLOFF, int NWORD>
__device__ float conf_work(int b, int bl, int chunk,
                           const float* __restrict__ yt,
                           const float* __restrict__ pred,
                           float4* sA, float* sArea, int* s_wtot) {
    constexpr int SEGLEN = W * W * 3;
    constexpr float invW = 1.f / (float)W;
    const float* segbase = yt + ((size_t)b * 3549 + CELLOFF) * 255;

    // ---- hoisted pred loads: independent of k_mask, issued BEFORE the
    //      grid-dependency sync so they overlap the producer kernel.
    float q0[2], q1[2], q2[2], q3[2], q4[2];
    bool valid[2];
    int locs[2];
    #pragma unroll
    for (int j = 0; j < 2; j++) {
        int loc = chunk * 512 + j * 256 + threadIdx.x;
        locs[j] = loc;
        valid[j] = (loc < SEGLEN);
        int locc = valid[j] ? loc : 0;
        const float* pb = pred + (size_t)b * (W * W * 255) + (size_t)locc * 85;
        q0[j] = __ldg(pb);
        q1[j] = __ldg(pb + 1); q2[j] = __ldg(pb + 2);
        q3[j] = __ldg(pb + 3); q4[j] = __ldg(pb + 4);
    }

    cudaGridDependencySynchronize();   // k_mask complete; g_mask visible

    bool objb[2];
    #pragma unroll
    for (int j = 0; j < 2; j++) {
        int locc = valid[j] ? locs[j] : 0;
        unsigned mw = g_mask[bl * 256 + (locc >> 5)];
        objb[j] = (mw >> (locc & 31)) & 1u;
    }

    int total = build_list(bl, NWORD, segbase, sA, sArea, nullptr, s_wtot);
    int cnt = min(total, 64);

    // ---- geometry + conf bce
    float pminx[2], pminy[2], pmaxx[2], pmaxy[2], pa[2], cb[2];
    bool hit[2];
    #pragma unroll
    for (int j = 0; j < 2; j++) {
        hit[j] = false;
        cb[j] = 0.f;
        pminx[j] = pmaxx[j] = pminy[j] = pmaxy[j] = pa[j] = 0.f;
        if (valid[j]) {
            int loc = locs[j];
            int cell = loc / 3, a = loc - cell * 3;
            int hh = cell / W, ww = cell - hh * W;
            float aw = c_anc[3 * LAYER + a][0];
            float ah = c_anc[3 * LAYER + a][1];
            float bx = (sigf(q1[j]) + (float)ww) * invW;
            float by = (sigf(q2[j]) + (float)hh) * invW;
            float bw = __expf(q3[j]) * (aw * invW);
            float bh = __expf(q4[j]) * (ah * invW);
            float hx = 0.5f * bw, hy = 0.5f * bh;
            pminx[j] = bx - hx; pmaxx[j] = bx + hx;
            pminy[j] = by - hy; pmaxy[j] = by + hy;
            pa[j] = bw * bh;
            cb[j] = bce01(objb[j] ? 1.f : 0.f, sigf(q0[j]));
        }
    }

    for (int k = 0; k < cnt; k++) {
        float4 A = sA[k];
        float ta = sArea[k];
        #pragma unroll
        for (int j = 0; j < 2; j++) {
            float iw = fminf(pmaxx[j], A.z) - fmaxf(pminx[j], A.x);
            float ih = fminf(pmaxy[j], A.w) - fmaxf(pminy[j], A.y);
            float inter = fmaxf(iw, 0.f) * fmaxf(ih, 0.f);
            hit[j] = hit[j] || (3.f * inter >= pa[j] + ta);   // iou >= 0.5
        }
    }

    float lsum = 0.f;
    #pragma unroll
    for (int j = 0; j < 2; j++)
        if (valid[j]) lsum += cb[j] * (objb[j] ? 1.f : (hit[j] ? 0.f : 1.f));
    return lsum;
}

// ============================ positive path ==================================
template<int W, int LAYER, int CELLOFF, int NWORD>
__device__ void pos_work(int b, int bl,
                         const float* __restrict__ yt,
                         const float* __restrict__ pred,
                         float* __restrict__ out,
                         float4* sA, float* sArea, int* s_loc, int* s_wtot,
                         float* s_red) {
    constexpr float fW = (float)W;
    constexpr float invW = 1.f / (float)W;
    const float* segbase = yt + ((size_t)b * 3549 + CELLOFF) * 255;

    cudaGridDependencySynchronize();   // need g_mask before anything

    int total = build_list(bl, NWORD, segbase, sA, sArea, s_loc, s_wtot);
    int pcnt = min(total, PMAX);
    if (pcnt == 0) return;

    const float* pbase = pred + (size_t)b * (W * W * 255);
    int wid = threadIdx.x >> 5, lane = threadIdx.x & 31;

    float acc = 0.f;
    for (int k = wid; k < pcnt; k += 8) {
        int loc = s_loc[k];
        int cell = loc / 3, a = loc - cell * 3;
        int hh = cell / W, ww = cell - hh * W;
        const float* tb = segbase + (size_t)loc * 85;
        const float* pb = pbase + (size_t)loc * 85;
        float aw = c_anc[3 * LAYER + a][0];
        float ah = c_anc[3 * LAYER + a][1];

        // group 0: channels 1..32
        float t0 = __ldg(tb + lane + 1), q0 = __ldg(pb + lane + 1);
        float tw = __shfl_sync(FULLM, t0, 2);    // yt ch3
        float th = __shfl_sync(FULLM, t0, 3);    // yt ch4
        float scale = 2.f - tw * th;
        float l = 0.f;
        if (lane == 0) {          // x
            float x = (sigf(q0) + (float)ww) * invW;
            float t = t0 * fW - (float)ww;
            l = scale * bce01(t, x);
        } else if (lane == 1) {   // y
            float x = (sigf(q0) + (float)hh) * invW;
            float t = t0 * fW - (float)hh;
            l = scale * bce01(t, x);
        } else if (lane == 2) {   // w
            float wp = __expf(q0) * aw * invW;
            float t = __logf(t0 * (416.f / aw));
            float d = t - wp;
            l = scale * 0.5f * d * d;
        } else if (lane == 3) {   // h
            float hp = __expf(q0) * ah * invW;
            float t = __logf(t0 * (416.f / ah));
            float d = t - hp;
            l = scale * 0.5f * d * d;
        } else {                  // cls channels 5..32
            l = bce01(t0, sigf(q0));
        }
        // group 1: channels 33..64 (cls)
        float t1 = __ldg(tb + lane + 33), q1 = __ldg(pb + lane + 33);
        l += bce01(t1, sigf(q1));
        // group 2: channels 65..84 (cls)
        if (lane < 20) {
            float t2 = __ldg(tb + lane + 65), q2 = __ldg(pb + lane + 65);
            l += bce01(t2, sigf(q2));
        }
        acc += l;
    }
    #pragma unroll
    for (int o = 16; o; o >>= 1) acc += __shfl_xor_sync(FULLM, acc, o);
    if (lane == 0) s_red[wid] = acc;
    __syncthreads();
    if (threadIdx.x == 0) {
        float v = 0.f;
        #pragma unroll
        for (int i = 0; i < 8; i++) v += s_red[i];
        if (v != 0.f) atomicAdd(out + b, v);
    }
}

// ============================ k_main =========================================
__global__ __launch_bounds__(256, 6)
void k_main(const float* __restrict__ yt,
            const float* __restrict__ p13,
            const float* __restrict__ p26,
            const float* __restrict__ p52,
            float* __restrict__ out) {
    __shared__ float4 sA[64];
    __shared__ float  sArea[64];
    __shared__ int    s_loc[PMAX];
    __shared__ int    s_wtot[8];
    __shared__ float  s_red[8];

    int blk = blockIdx.x;
    if (blk < NBL) {
        int b = blk / 3, layer = blk - b * 3;
        if (layer == 0)
            pos_work<13, 0, 0, 16>  (b, blk, yt, p13, out, sA, sArea, s_loc, s_wtot, s_red);
        else if (layer == 1)
            pos_work<26, 1, 169, 64>(b, blk, yt, p26, out, sA, sArea, s_loc, s_wtot, s_red);
        else
            pos_work<52, 2, 845, 254>(b, blk, yt, p52, out, sA, sArea, s_loc, s_wtot, s_red);
        return;
    }

    blk -= NBL;
    int b = blk / 21, r = blk - b * 21;
    int layer, chunk;
    rmap21(r, layer, chunk);
    int bl = b * 3 + layer;

    float lsum;
    if (layer == 0)
        lsum = conf_work<13, 0, 0, 16>  (b, bl, chunk, yt, p13, sA, sArea, s_wtot);
    else if (layer == 1)
        lsum = conf_work<26, 1, 169, 64>(b, bl, chunk, yt, p26, sA, sArea, s_wtot);
    else
        lsum = conf_work<52, 2, 845, 254>(b, bl, chunk, yt, p52, sA, sArea, s_wtot);

    #pragma unroll
    for (int o = 16; o; o >>= 1) lsum += __shfl_xor_sync(FULLM, lsum, o);
    int wid = threadIdx.x >> 5, lane = threadIdx.x & 31;
    if (lane == 0) s_red[wid] = lsum;
    __syncthreads();
    if (threadIdx.x == 0) {
        float v = 0.f;
        #pragma unroll
        for (int i = 0; i < 8; i++) v += s_red[i];
        atomicAdd(out + b, v);
    }
}

// ---------------------------------------------------------------------------
extern "C" void kernel_launch(void* const* d_in, const int* in_sizes, int n_in,
                              void* d_out, int out_size) {
    const float* yt  = (const float*)d_in[0];
    const float* p13 = (const float*)d_in[1];
    const float* p26 = (const float*)d_in[2];
    const float* p52 = (const float*)d_in[3];
    float* out = (float*)d_out;

    k_mask<<<NB * 21, 256>>>(yt, out);

    // programmatic dependent launch: k_main may start while k_mask runs;
    // it gates on cudaGridDependencySynchronize() before reading g_mask.
    cudaLaunchConfig_t cfg = {};
    cfg.gridDim  = dim3(NBL + NB * 21, 1, 1);   // 768
    cfg.blockDim = dim3(256, 1, 1);
    cfg.dynamicSmemBytes = 0;
    cfg.stream = 0;
    cudaLaunchAttribute attrs[1];
    attrs[0].id = cudaLaunchAttributeProgrammaticStreamSerialization;
    attrs[0].val.programmaticStreamSerializationAllowed = 1;
    cfg.attrs = attrs;
    cfg.numAttrs = 1;
    cudaLaunchKernelEx(&cfg, k_main, yt, p13, p26, p52, out);
}